// round 14
// baseline (speedup 1.0000x reference)
#include <cuda_runtime.h>
#include <math.h>
#include <stdint.h>

#define T_SEQ   4096
#define C_DIM   1024
#define NHEADS  16
#define HDIM    64

// ---------------- scratch (static device globals; no allocation) -------------
__device__ float g_normed[T_SEQ * C_DIM];
__device__ float g_q[T_SEQ * C_DIM];
__device__ float g_k[T_SEQ * C_DIM];
__device__ float g_v[T_SEQ * C_DIM];
__device__ float g_qp[T_SEQ * C_DIM];      // d-permuted, scaled, tf32 q
__device__ float g_kp[T_SEQ * C_DIM];      // d-permuted, tf32 k
__device__ float g_att[T_SEQ * C_DIM];
__device__ float g_wr[4][C_DIM * C_DIM];   // tf32-rounded weights

// ================= helpers ===================================================
__device__ __forceinline__ uint32_t smem_u32(const void* p) {
    uint32_t a;
    asm("{ .reg .u64 t; cvta.to.shared.u64 t, %1; cvt.u32.u64 %0, t; }"
        : "=r"(a) : "l"(p));
    return a;
}

__device__ __forceinline__ void cp_async16(uint32_t saddr, const void* gptr) {
    asm volatile("cp.async.cg.shared.global [%0], [%1], 16;"
                 :: "r"(saddr), "l"(gptr));
}
__device__ __forceinline__ void cp_commit() {
    asm volatile("cp.async.commit_group;");
}
template <int N>
__device__ __forceinline__ void cp_wait() {
    asm volatile("cp.async.wait_group %0;" :: "n"(N));
}

__device__ __forceinline__ float to_tf32(float a)
{
    uint32_t u;
    asm("cvt.rna.tf32.f32 %0, %1;" : "=r"(u) : "f"(a));
    return __uint_as_float(u);
}

// m16n8k8 tf32 mma
__device__ __forceinline__ void mma_tf32(float d[4],
                                         float a0, float a1, float a2, float a3,
                                         float b0, float b1)
{
    asm volatile(
        "mma.sync.aligned.m16n8k8.row.col.f32.tf32.tf32.f32 "
        "{%0,%1,%2,%3}, {%4,%5,%6,%7}, {%8,%9}, {%0,%1,%2,%3};"
        : "+f"(d[0]), "+f"(d[1]), "+f"(d[2]), "+f"(d[3])
        : "r"(__float_as_uint(a0)), "r"(__float_as_uint(a1)),
          "r"(__float_as_uint(a2)), "r"(__float_as_uint(a3)),
          "r"(__float_as_uint(b0)), "r"(__float_as_uint(b1)));
}

// ---------------- batched tf32 rounding of the 4 weight matrices -------------
__global__ void round_weights_kernel(const float* __restrict__ w0,
                                     const float* __restrict__ w1,
                                     const float* __restrict__ w2,
                                     const float* __restrict__ w3,
                                     float* __restrict__ outbase, int n4)
{
    int i = blockIdx.x * blockDim.x + threadIdx.x;
    if (i >= n4) return;
    int wsel = blockIdx.y;
    const float* in = (wsel == 0) ? w0 : (wsel == 1) ? w1 : (wsel == 2) ? w2 : w3;
    float* out = outbase + (size_t)wsel * C_DIM * C_DIM;
    float4 v = reinterpret_cast<const float4*>(in)[i];
    v.x = to_tf32(v.x); v.y = to_tf32(v.y);
    v.z = to_tf32(v.z); v.w = to_tf32(v.w);
    reinterpret_cast<float4*>(out)[i] = v;
}

// ================= HMMA tf32 GEMM body (pre-rounded inputs) ==================
#define G_BM 128
#define G_BN 128
#define G_BK 32
#define G_SK 36
#define G_PLANE (128 * G_SK)
#define G_STAGE (2 * G_PLANE)
#define G_SMEM_TOTAL (2 * G_STAGE * 4)        // 73728 bytes

__device__ __forceinline__ void issue_tile(uint32_t s_a, uint32_t s_b,
                                           const float* __restrict__ Ag,
                                           const float* __restrict__ Bg,
                                           int K, int k0, int tid)
{
#pragma unroll
    for (int t = 0; t < 4; t++) {
        int idx = tid + t * 256;
        int row = idx >> 3;
        int c4 = idx & 7;
        uint32_t soff = (uint32_t)(row * G_SK + c4 * 4) * 4u;
        cp_async16(s_a + soff, Ag + (size_t)row * K + k0 + c4 * 4);
        cp_async16(s_b + soff, Bg + (size_t)row * K + k0 + c4 * 4);
    }
}

__device__ __forceinline__ void gemm_body(const float* __restrict__ A,
                                          const float* __restrict__ B,
                                          const float* __restrict__ Res,
                                          float* __restrict__ Cm,
                                          int M, int N, int K,
                                          int bx, int by, float* sm)
{
    uint32_t smem_base = smem_u32(sm);
    int tid = threadIdx.x;
    int wid = tid >> 5;
    int lane = tid & 31;
    int gid = lane >> 2;
    int tig = lane & 3;
    int wm = wid & 1;
    int wn = wid >> 1;

    const float* Atile = A + (size_t)(by * G_BM) * K;
    const float* Btile = B + (size_t)(bx * G_BN) * K;

    float acc[4][4][4];
#pragma unroll
    for (int mi = 0; mi < 4; mi++)
#pragma unroll
        for (int ni = 0; ni < 4; ni++)
#pragma unroll
            for (int e = 0; e < 4; e++) acc[mi][ni][e] = 0.f;

    const int NCHUNK = K / G_BK;

    issue_tile(smem_base, smem_base + G_PLANE * 4u, Atile, Btile, K, 0, tid);
    cp_commit();

    for (int kc = 0; kc < NCHUNK; kc++) {
        int cur = kc & 1;
        if (kc + 1 < NCHUNK) {
            uint32_t sb = smem_base + (uint32_t)(1 - cur) * G_STAGE * 4u;
            issue_tile(sb, sb + G_PLANE * 4u, Atile, Btile, K, (kc + 1) * G_BK, tid);
            cp_commit();
            cp_wait<1>();
        } else {
            cp_wait<0>();
        }
        __syncthreads();

        const float* As = sm + cur * G_STAGE;
        const float* Bs = As + G_PLANE;

#pragma unroll
        for (int ks = 0; ks < 4; ks++) {
            int kk = ks * 8;
            float Ah[4][4];
#pragma unroll
            for (int mi = 0; mi < 4; mi++) {
                int mrow = wm * 64 + mi * 16 + gid;
                int base = mrow * G_SK + kk + tig;
                Ah[mi][0] = As[base];
                Ah[mi][1] = As[base + 8 * G_SK];
                Ah[mi][2] = As[base + 4];
                Ah[mi][3] = As[base + 8 * G_SK + 4];
            }
            float Bh[4][2];
#pragma unroll
            for (int ni = 0; ni < 4; ni++) {
                int ncol = wn * 32 + ni * 8 + gid;
                int base = ncol * G_SK + kk + tig;
                Bh[ni][0] = Bs[base];
                Bh[ni][1] = Bs[base + 4];
            }
#pragma unroll
            for (int mi = 0; mi < 4; mi++)
#pragma unroll
                for (int ni = 0; ni < 4; ni++)
                    mma_tf32(acc[mi][ni], Ah[mi][0], Ah[mi][1], Ah[mi][2], Ah[mi][3],
                             Bh[ni][0], Bh[ni][1]);
        }
        __syncthreads();
    }

#pragma unroll
    for (int mi = 0; mi < 4; mi++) {
        int row0 = by * G_BM + wm * 64 + mi * 16 + gid;
#pragma unroll
        for (int ni = 0; ni < 4; ni++) {
            int col = bx * G_BN + wn * 32 + ni * 8 + 2 * tig;
            float* d0 = Cm + (size_t)row0 * N + col;
            float* d1 = Cm + (size_t)(row0 + 8) * N + col;
            float2 v0 = make_float2(acc[mi][ni][0], acc[mi][ni][1]);
            float2 v1 = make_float2(acc[mi][ni][2], acc[mi][ni][3]);
            if (Res) {
                const float2 r0 = *reinterpret_cast<const float2*>(Res + (size_t)row0 * N + col);
                const float2 r1 = *reinterpret_cast<const float2*>(Res + (size_t)(row0 + 8) * N + col);
                v0.x += r0.x; v0.y += r0.y;
                v1.x += r1.x; v1.y += r1.y;
            }
            *reinterpret_cast<float2*>(d0) = v0;
            *reinterpret_cast<float2*>(d1) = v1;
        }
    }
}

__global__ __launch_bounds__(256, 2)
void gemm_qkv_kernel(const float* __restrict__ A,
                     const float* __restrict__ b0, const float* __restrict__ b1,
                     const float* __restrict__ b2,
                     float* __restrict__ c0, float* __restrict__ c1,
                     float* __restrict__ c2)
{
    extern __shared__ float sm[];
    int z = blockIdx.z;
    const float* B = (z == 0) ? b0 : (z == 1) ? b1 : b2;
    float* Cm = (z == 0) ? c0 : (z == 1) ? c1 : c2;
    gemm_body(A, B, nullptr, Cm, T_SEQ, C_DIM, C_DIM, blockIdx.x, blockIdx.y, sm);
}

__global__ __launch_bounds__(256, 2)
void gemm_mma_kernel(const float* __restrict__ A, const float* __restrict__ B,
                     const float* __restrict__ Res, float* __restrict__ Cm,
                     int M, int N, int K)
{
    extern __shared__ float sm[];
    gemm_body(A, B, Res, Cm, M, N, K, blockIdx.x, blockIdx.y, sm);
}

// ---------------- RMSNorm (output rounded to tf32 — GEMM A operand) ----------
__global__ void rmsnorm_kernel(const float* __restrict__ x,
                               const float* __restrict__ w,
                               float* __restrict__ out)
{
    int row = blockIdx.x;
    const float4* xr = reinterpret_cast<const float4*>(x + (size_t)row * C_DIM);
    float ss = 0.f;
    for (int i = threadIdx.x; i < C_DIM / 4; i += blockDim.x) {
        float4 v = xr[i];
        ss += v.x * v.x + v.y * v.y + v.z * v.z + v.w * v.w;
    }
#pragma unroll
    for (int o = 16; o; o >>= 1) ss += __shfl_xor_sync(0xffffffffu, ss, o);

    __shared__ float red[8];
    __shared__ float s_inv;
    if ((threadIdx.x & 31) == 0) red[threadIdx.x >> 5] = ss;
    __syncthreads();
    if (threadIdx.x == 0) {
        float tot = 0.f;
        int nw = blockDim.x >> 5;
        for (int i = 0; i < nw; i++) tot += red[i];
        s_inv = rsqrtf(tot * (1.0f / C_DIM) + 1e-6f);
    }
    __syncthreads();
    float inv = s_inv;
    const float4* wr = reinterpret_cast<const float4*>(w);
    float4* outr = reinterpret_cast<float4*>(out + (size_t)row * C_DIM);
    for (int i = threadIdx.x; i < C_DIM / 4; i += blockDim.x) {
        float4 v = xr[i], ww = wr[i];
        v.x = to_tf32(v.x * inv * ww.x);
        v.y = to_tf32(v.y * inv * ww.y);
        v.z = to_tf32(v.z * inv * ww.z);
        v.w = to_tf32(v.w * inv * ww.w);
        outr[i] = v;
    }
}

// ---------------- RoPE + d-permutation + flash-operand rounding --------------
// Within each 8-group of headdim, permuted order (0,4,1,5,2,6,3,7): the tf32
// fragment pair (k=t, k=t+4) becomes adjacent -> float2 LDS in flash.
// Thread handles permuted DEST positions (p, p+32); reads the inverse-permuted
// source rotation pair from q/k; writes to separate buffers (no in-place race).
// v is rounded elementwise in place (no permutation).
__global__ void rope_kernel(const float* __restrict__ q, const float* __restrict__ k,
                            float* __restrict__ v,
                            float* __restrict__ qp, float* __restrict__ kp)
{
    int idx = blockIdx.x * blockDim.x + threadIdx.x;
    if (idx >= T_SEQ * NHEADS * 32) return;
    int p = idx & 31;
    int h = (idx >> 5) & (NHEADS - 1);
    int t = idx >> 9;
    int j = p & 7;
    int i0 = (p & ~7) | ((j & 1) ? ((j >> 1) + 4) : (j >> 1));   // source index
    float freq = powf(10000.0f, -(float)(2 * i0) * (1.0f / 64.0f));
    float f = (float)t * freq;
    float s, c;
    sincosf(f, &s, &c);
    int base = t * C_DIM + h * HDIM;
    float q1 = q[base + i0], q2 = q[base + i0 + 32];
    qp[base + p]      = to_tf32((q1 * c - q2 * s) * 0.125f);
    qp[base + p + 32] = to_tf32((q2 * c + q1 * s) * 0.125f);
    float k1 = k[base + i0], k2 = k[base + i0 + 32];
    kp[base + p]      = to_tf32(k1 * c - k2 * s);
    kp[base + p + 32] = to_tf32(k2 * c + k1 * s);
    v[base + p]       = to_tf32(v[base + p]);
    v[base + p + 32]  = to_tf32(v[base + p + 32]);
}

// ---------------- Flash attention on tensor cores ----------------------------
// Br=Bc=64, 4 warps, 1-term tf32, occ=3. Q/K d-permuted -> float2 fragment LDS.
#define FQ_STR 68
#define FV_STR 72
#define F_SMEM_BYTES ((3 * 64 * FQ_STR + 64 * FV_STR) * 4)   // 70656

__global__ __launch_bounds__(128, 3)
void flash_mma_kernel(const float* __restrict__ Qg, const float* __restrict__ Kg,
                      const float* __restrict__ Vg, float* __restrict__ Og)
{
    extern __shared__ float sm[];
    float* Qs = sm;
    float* Kh = Qs + 64 * FQ_STR;
    float* Ps = Kh + 64 * FQ_STR;
    float* Vs = Ps + 64 * FQ_STR;
    uint32_t kh_base = smem_u32(Kh);
    uint32_t vs_base = smem_u32(Vs);

    int qt = (gridDim.x - 1) - blockIdx.x;   // heavy tiles first
    int h  = blockIdx.y;
    int tid = threadIdx.x;
    int wid = tid >> 5;
    int lane = tid & 31;
    int gid = lane >> 2;
    int tig = lane & 3;
    int wr0 = wid * 16;

    // ---- load Q tile (pre-permuted/scaled/rounded) ----
#pragma unroll
    for (int v = 0; v < 8; v++) {
        int i = tid + v * 128;
        int row = i >> 4;
        int c4 = i & 15;
        *reinterpret_cast<float4*>(Qs + row * FQ_STR + c4 * 4) =
            *reinterpret_cast<const float4*>(
                Qg + (size_t)(qt * 64 + row) * C_DIM + h * HDIM + c4 * 4);
    }

    float oacc[8][4];
#pragma unroll
    for (int ni = 0; ni < 8; ni++)
#pragma unroll
        for (int e = 0; e < 4; e++) oacc[ni][e] = 0.f;
    float m0 = -INFINITY, m1 = -INFINITY;
    float l0 = 0.f, l1 = 0.f;

    for (int j = 0; j <= qt; j++) {
        __syncthreads();

        // ---- stage K and V tiles via cp.async (pre-rounded data) ----
#pragma unroll
        for (int t = 0; t < 8; t++) {
            int i = tid + t * 128;
            int row = i >> 4;
            int c4 = i & 15;
            const float* kg = Kg + (size_t)(j * 64 + row) * C_DIM + h * HDIM + c4 * 4;
            const float* vg = Vg + (size_t)(j * 64 + row) * C_DIM + h * HDIM + c4 * 4;
            cp_async16(kh_base + (uint32_t)(row * FQ_STR + c4 * 4) * 4u, kg);
            cp_async16(vs_base + (uint32_t)(row * FV_STR + c4 * 4) * 4u, vg);
        }
        cp_commit();
        cp_wait<0>();
        __syncthreads();

        // ---- S = Q K^T (float2 fragment loads via d-permutation) ----
        float sacc[8][4];
#pragma unroll
        for (int ni = 0; ni < 8; ni++)
#pragma unroll
            for (int e = 0; e < 4; e++) sacc[ni][e] = 0.f;

#pragma unroll
        for (int kk = 0; kk < 8; kk++) {
            int kb = kk * 8;
            int abase = (wr0 + gid) * FQ_STR + kb + 2 * tig;
            float2 qA = *reinterpret_cast<const float2*>(Qs + abase);            // a0,a2
            float2 qB = *reinterpret_cast<const float2*>(Qs + abase + 8 * FQ_STR); // a1,a3
#pragma unroll
            for (int ni = 0; ni < 8; ni++) {
                float2 b = *reinterpret_cast<const float2*>(
                    Kh + (ni * 8 + gid) * FQ_STR + kb + 2 * tig);                 // b0,b1
                mma_tf32(sacc[ni], qA.x, qB.x, qA.y, qB.y, b.x, b.y);
            }
        }

        if (j == qt) {
#pragma unroll
            for (int ni = 0; ni < 8; ni++) {
                int c0 = ni * 8 + 2 * tig;
                int rA = wr0 + gid, rB = wr0 + gid + 8;
                if (c0 > rA)     sacc[ni][0] = -INFINITY;
                if (c0 + 1 > rA) sacc[ni][1] = -INFINITY;
                if (c0 > rB)     sacc[ni][2] = -INFINITY;
                if (c0 + 1 > rB) sacc[ni][3] = -INFINITY;
            }
        }

        float rm0 = -INFINITY, rm1 = -INFINITY;
#pragma unroll
        for (int ni = 0; ni < 8; ni++) {
            rm0 = fmaxf(rm0, fmaxf(sacc[ni][0], sacc[ni][1]));
            rm1 = fmaxf(rm1, fmaxf(sacc[ni][2], sacc[ni][3]));
        }
        rm0 = fmaxf(rm0, __shfl_xor_sync(0xffffffffu, rm0, 1));
        rm0 = fmaxf(rm0, __shfl_xor_sync(0xffffffffu, rm0, 2));
        rm1 = fmaxf(rm1, __shfl_xor_sync(0xffffffffu, rm1, 1));
        rm1 = fmaxf(rm1, __shfl_xor_sync(0xffffffffu, rm1, 2));

        float mn0 = fmaxf(m0, rm0);
        float mn1 = fmaxf(m1, rm1);
        float alpha0 = __expf(m0 - mn0);
        float alpha1 = __expf(m1 - mn1);
        m0 = mn0; m1 = mn1;

        float rs0 = 0.f, rs1 = 0.f;
#pragma unroll
        for (int ni = 0; ni < 8; ni++) {
            float p0 = __expf(sacc[ni][0] - mn0);
            float p1 = __expf(sacc[ni][1] - mn0);
            float p2 = __expf(sacc[ni][2] - mn1);
            float p3 = __expf(sacc[ni][3] - mn1);
            rs0 += p0 + p1;
            rs1 += p2 + p3;
            int c0 = ni * 8 + 2 * tig;
            *reinterpret_cast<float2*>(Ps + (wr0 + gid) * FQ_STR + c0) =
                make_float2(to_tf32(p0), to_tf32(p1));
            *reinterpret_cast<float2*>(Ps + (wr0 + gid + 8) * FQ_STR + c0) =
                make_float2(to_tf32(p2), to_tf32(p3));
        }
        rs0 += __shfl_xor_sync(0xffffffffu, rs0, 1);
        rs0 += __shfl_xor_sync(0xffffffffu, rs0, 2);
        rs1 += __shfl_xor_sync(0xffffffffu, rs1, 1);
        rs1 += __shfl_xor_sync(0xffffffffu, rs1, 2);
        l0 = l0 * alpha0 + rs0;
        l1 = l1 * alpha1 + rs1;

#pragma unroll
        for (int ni = 0; ni < 8; ni++) {
            oacc[ni][0] *= alpha0; oacc[ni][1] *= alpha0;
            oacc[ni][2] *= alpha1; oacc[ni][3] *= alpha1;
        }
        __syncwarp();

        // ---- O += P V ----
#pragma unroll
        for (int kk = 0; kk < 8; kk++) {
            int kb = kk * 8;
            int abase = (wr0 + gid) * FQ_STR + kb + tig;
            float a0 = Ps[abase];
            float a1 = Ps[abase + 8 * FQ_STR];
            float a2 = Ps[abase + 4];
            float a3 = Ps[abase + 8 * FQ_STR + 4];
#pragma unroll
            for (int ni = 0; ni < 8; ni++) {
                float b0 = Vs[(kb + tig) * FV_STR + ni * 8 + gid];
                float b1 = Vs[(kb + tig + 4) * FV_STR + ni * 8 + gid];
                mma_tf32(oacc[ni], a0, a1, a2, a3, b0, b1);
            }
        }
    }

    float invl0 = 1.f / l0;
    float invl1 = 1.f / l1;
    int row0 = qt * 64 + wr0 + gid;
    int row1 = row0 + 8;
#pragma unroll
    for (int ni = 0; ni < 8; ni++) {
        int col = h * HDIM + ni * 8 + 2 * tig;
        *reinterpret_cast<float2*>(Og + (size_t)row0 * C_DIM + col) =
            make_float2(to_tf32(oacc[ni][0] * invl0), to_tf32(oacc[ni][1] * invl0));
        *reinterpret_cast<float2*>(Og + (size_t)row1 * C_DIM + col) =
            make_float2(to_tf32(oacc[ni][2] * invl1), to_tf32(oacc[ni][3] * invl1));
    }
}

// ---------------- launch -----------------------------------------------------
extern "C" void kernel_launch(void* const* d_in, const int* in_sizes, int n_in,
                              void* d_out, int out_size)
{
    const float* x      = (const float*)d_in[0];
    const float* wq     = (const float*)d_in[1];
    const float* wk     = (const float*)d_in[2];
    const float* wv     = (const float*)d_in[3];
    const float* wo     = (const float*)d_in[4];
    const float* norm_w = (const float*)d_in[5];
    float* out = (float*)d_out;

    float *normed, *q, *k, *v, *qp, *kp, *att, *wr;
    cudaGetSymbolAddress((void**)&normed, g_normed);
    cudaGetSymbolAddress((void**)&q,      g_q);
    cudaGetSymbolAddress((void**)&k,      g_k);
    cudaGetSymbolAddress((void**)&v,      g_v);
    cudaGetSymbolAddress((void**)&qp,     g_qp);
    cudaGetSymbolAddress((void**)&kp,     g_kp);
    cudaGetSymbolAddress((void**)&att,    g_att);
    cudaGetSymbolAddress((void**)&wr,     g_wr);
    float* wqr = wr + 0 * C_DIM * C_DIM;
    float* wkr = wr + 1 * C_DIM * C_DIM;
    float* wvr = wr + 2 * C_DIM * C_DIM;
    float* wor = wr + 3 * C_DIM * C_DIM;

    // 0) round all 4 weight matrices to tf32 in one batched launch
    int n4 = C_DIM * C_DIM / 4;
    dim3 rg((n4 + 255) / 256, 4);
    round_weights_kernel<<<rg, 256>>>(wq, wk, wv, wo, wr, n4);

    // 1) RMSNorm (emits tf32-rounded A operand)
    rmsnorm_kernel<<<T_SEQ, 256>>>(x, norm_w, normed);

    // 2) Q/K/V projections: one batched launch
    cudaFuncSetAttribute(gemm_qkv_kernel, cudaFuncAttributeMaxDynamicSharedMemorySize,
                         G_SMEM_TOTAL);
    cudaFuncSetAttribute(gemm_mma_kernel, cudaFuncAttributeMaxDynamicSharedMemorySize,
                         G_SMEM_TOTAL);
    dim3 gqkv(C_DIM / G_BN, T_SEQ / G_BM, 3);
    gemm_qkv_kernel<<<gqkv, 256, G_SMEM_TOTAL>>>(normed, wqr, wkr, wvr, q, k, v);

    // 3) RoPE + d-permutation + rounding for flash
    int nrope = T_SEQ * NHEADS * 32;
    rope_kernel<<<(nrope + 255) / 256, 256>>>(q, k, v, qp, kp);

    // 4) causal flash attention (permuted Q/K, float2 fragment loads)
    cudaFuncSetAttribute(flash_mma_kernel, cudaFuncAttributeMaxDynamicSharedMemorySize,
                         F_SMEM_BYTES);
    dim3 fgrid(T_SEQ / 64, NHEADS);
    flash_mma_kernel<<<fgrid, 128, F_SMEM_BYTES>>>(qp, kp, v, att);

    // 5) output projection + residual
    dim3 gdim(C_DIM / G_BN, T_SEQ / G_BM);
    gemm_mma_kernel<<<gdim, 256, G_SMEM_TOTAL>>>(att, wor, x, out, T_SEQ, C_DIM, C_DIM);
}

// round 16
// speedup vs baseline: 1.1361x; 1.1361x over previous
#include <cuda_runtime.h>
#include <math.h>
#include <stdint.h>

#define T_SEQ   4096
#define C_DIM   1024
#define NHEADS  16
#define HDIM    64

// ---------------- scratch (static device globals; no allocation) -------------
__device__ float g_normed[T_SEQ * C_DIM];
__device__ float g_q[T_SEQ * C_DIM];
__device__ float g_k[T_SEQ * C_DIM];
__device__ float g_v[T_SEQ * C_DIM];
__device__ float g_qp[T_SEQ * C_DIM];      // d-permuted, scaled, tf32 q
__device__ float g_kp[T_SEQ * C_DIM];      // d-permuted, tf32 k
__device__ float g_att[T_SEQ * C_DIM];
__device__ float g_wr[4][C_DIM * C_DIM];   // tf32-rounded weights

// ================= helpers ===================================================
__device__ __forceinline__ uint32_t smem_u32(const void* p) {
    uint32_t a;
    asm("{ .reg .u64 t; cvta.to.shared.u64 t, %1; cvt.u32.u64 %0, t; }"
        : "=r"(a) : "l"(p));
    return a;
}

__device__ __forceinline__ void cp_async16(uint32_t saddr, const void* gptr) {
    asm volatile("cp.async.cg.shared.global [%0], [%1], 16;"
                 :: "r"(saddr), "l"(gptr));
}
__device__ __forceinline__ void cp_commit() {
    asm volatile("cp.async.commit_group;");
}
template <int N>
__device__ __forceinline__ void cp_wait() {
    asm volatile("cp.async.wait_group %0;" :: "n"(N));
}

__device__ __forceinline__ float to_tf32(float a)
{
    uint32_t u;
    asm("cvt.rna.tf32.f32 %0, %1;" : "=r"(u) : "f"(a));
    return __uint_as_float(u);
}

// m16n8k8 tf32 mma
__device__ __forceinline__ void mma_tf32(float d[4],
                                         float a0, float a1, float a2, float a3,
                                         float b0, float b1)
{
    asm volatile(
        "mma.sync.aligned.m16n8k8.row.col.f32.tf32.tf32.f32 "
        "{%0,%1,%2,%3}, {%4,%5,%6,%7}, {%8,%9}, {%0,%1,%2,%3};"
        : "+f"(d[0]), "+f"(d[1]), "+f"(d[2]), "+f"(d[3])
        : "r"(__float_as_uint(a0)), "r"(__float_as_uint(a1)),
          "r"(__float_as_uint(a2)), "r"(__float_as_uint(a3)),
          "r"(__float_as_uint(b0)), "r"(__float_as_uint(b1)));
}

// ---------------- batched tf32 rounding of the 4 weight matrices -------------
__global__ void round_weights_kernel(const float* __restrict__ w0,
                                     const float* __restrict__ w1,
                                     const float* __restrict__ w2,
                                     const float* __restrict__ w3,
                                     float* __restrict__ outbase, int n4)
{
    int i = blockIdx.x * blockDim.x + threadIdx.x;
    if (i >= n4) return;
    int wsel = blockIdx.y;
    const float* in = (wsel == 0) ? w0 : (wsel == 1) ? w1 : (wsel == 2) ? w2 : w3;
    float* out = outbase + (size_t)wsel * C_DIM * C_DIM;
    float4 v = reinterpret_cast<const float4*>(in)[i];
    v.x = to_tf32(v.x); v.y = to_tf32(v.y);
    v.z = to_tf32(v.z); v.w = to_tf32(v.w);
    reinterpret_cast<float4*>(out)[i] = v;
}

// ================= HMMA tf32 GEMM body (pre-rounded inputs) ==================
#define G_BM 128
#define G_BN 128
#define G_BK 32
#define G_SK 36
#define G_PLANE (128 * G_SK)
#define G_STAGE (2 * G_PLANE)
#define G_SMEM_TOTAL (2 * G_STAGE * 4)        // 73728 bytes

__device__ __forceinline__ void issue_tile(uint32_t s_a, uint32_t s_b,
                                           const float* __restrict__ Ag,
                                           const float* __restrict__ Bg,
                                           int K, int k0, int tid)
{
#pragma unroll
    for (int t = 0; t < 4; t++) {
        int idx = tid + t * 256;
        int row = idx >> 3;
        int c4 = idx & 7;
        uint32_t soff = (uint32_t)(row * G_SK + c4 * 4) * 4u;
        cp_async16(s_a + soff, Ag + (size_t)row * K + k0 + c4 * 4);
        cp_async16(s_b + soff, Bg + (size_t)row * K + k0 + c4 * 4);
    }
}

__device__ __forceinline__ void gemm_body(const float* __restrict__ A,
                                          const float* __restrict__ B,
                                          const float* __restrict__ Res,
                                          float* __restrict__ Cm,
                                          int M, int N, int K,
                                          int bx, int by, float* sm)
{
    uint32_t smem_base = smem_u32(sm);
    int tid = threadIdx.x;
    int wid = tid >> 5;
    int lane = tid & 31;
    int gid = lane >> 2;
    int tig = lane & 3;
    int wm = wid & 1;
    int wn = wid >> 1;

    const float* Atile = A + (size_t)(by * G_BM) * K;
    const float* Btile = B + (size_t)(bx * G_BN) * K;

    float acc[4][4][4];
#pragma unroll
    for (int mi = 0; mi < 4; mi++)
#pragma unroll
        for (int ni = 0; ni < 4; ni++)
#pragma unroll
            for (int e = 0; e < 4; e++) acc[mi][ni][e] = 0.f;

    const int NCHUNK = K / G_BK;

    issue_tile(smem_base, smem_base + G_PLANE * 4u, Atile, Btile, K, 0, tid);
    cp_commit();

    for (int kc = 0; kc < NCHUNK; kc++) {
        int cur = kc & 1;
        if (kc + 1 < NCHUNK) {
            uint32_t sb = smem_base + (uint32_t)(1 - cur) * G_STAGE * 4u;
            issue_tile(sb, sb + G_PLANE * 4u, Atile, Btile, K, (kc + 1) * G_BK, tid);
            cp_commit();
            cp_wait<1>();
        } else {
            cp_wait<0>();
        }
        __syncthreads();

        const float* As = sm + cur * G_STAGE;
        const float* Bs = As + G_PLANE;

#pragma unroll
        for (int ks = 0; ks < 4; ks++) {
            int kk = ks * 8;
            float Ah[4][4];
#pragma unroll
            for (int mi = 0; mi < 4; mi++) {
                int mrow = wm * 64 + mi * 16 + gid;
                int base = mrow * G_SK + kk + tig;
                Ah[mi][0] = As[base];
                Ah[mi][1] = As[base + 8 * G_SK];
                Ah[mi][2] = As[base + 4];
                Ah[mi][3] = As[base + 8 * G_SK + 4];
            }
            float Bh[4][2];
#pragma unroll
            for (int ni = 0; ni < 4; ni++) {
                int ncol = wn * 32 + ni * 8 + gid;
                int base = ncol * G_SK + kk + tig;
                Bh[ni][0] = Bs[base];
                Bh[ni][1] = Bs[base + 4];
            }
#pragma unroll
            for (int mi = 0; mi < 4; mi++)
#pragma unroll
                for (int ni = 0; ni < 4; ni++)
                    mma_tf32(acc[mi][ni], Ah[mi][0], Ah[mi][1], Ah[mi][2], Ah[mi][3],
                             Bh[ni][0], Bh[ni][1]);
        }
        __syncthreads();
    }

#pragma unroll
    for (int mi = 0; mi < 4; mi++) {
        int row0 = by * G_BM + wm * 64 + mi * 16 + gid;
#pragma unroll
        for (int ni = 0; ni < 4; ni++) {
            int col = bx * G_BN + wn * 32 + ni * 8 + 2 * tig;
            float* d0 = Cm + (size_t)row0 * N + col;
            float* d1 = Cm + (size_t)(row0 + 8) * N + col;
            float2 v0 = make_float2(acc[mi][ni][0], acc[mi][ni][1]);
            float2 v1 = make_float2(acc[mi][ni][2], acc[mi][ni][3]);
            if (Res) {
                const float2 r0 = *reinterpret_cast<const float2*>(Res + (size_t)row0 * N + col);
                const float2 r1 = *reinterpret_cast<const float2*>(Res + (size_t)(row0 + 8) * N + col);
                v0.x += r0.x; v0.y += r0.y;
                v1.x += r1.x; v1.y += r1.y;
            }
            *reinterpret_cast<float2*>(d0) = v0;
            *reinterpret_cast<float2*>(d1) = v1;
        }
    }
}

__global__ __launch_bounds__(256, 2)
void gemm_qkv_kernel(const float* __restrict__ A,
                     const float* __restrict__ b0, const float* __restrict__ b1,
                     const float* __restrict__ b2,
                     float* __restrict__ c0, float* __restrict__ c1,
                     float* __restrict__ c2)
{
    extern __shared__ float sm[];
    int z = blockIdx.z;
    const float* B = (z == 0) ? b0 : (z == 1) ? b1 : b2;
    float* Cm = (z == 0) ? c0 : (z == 1) ? c1 : c2;
    gemm_body(A, B, nullptr, Cm, T_SEQ, C_DIM, C_DIM, blockIdx.x, blockIdx.y, sm);
}

__global__ __launch_bounds__(256, 2)
void gemm_mma_kernel(const float* __restrict__ A, const float* __restrict__ B,
                     const float* __restrict__ Res, float* __restrict__ Cm,
                     int M, int N, int K)
{
    extern __shared__ float sm[];
    gemm_body(A, B, Res, Cm, M, N, K, blockIdx.x, blockIdx.y, sm);
}

// ---------------- RMSNorm (output rounded to tf32 — GEMM A operand) ----------
__global__ void rmsnorm_kernel(const float* __restrict__ x,
                               const float* __restrict__ w,
                               float* __restrict__ out)
{
    int row = blockIdx.x;
    const float4* xr = reinterpret_cast<const float4*>(x + (size_t)row * C_DIM);
    float ss = 0.f;
    for (int i = threadIdx.x; i < C_DIM / 4; i += blockDim.x) {
        float4 v = xr[i];
        ss += v.x * v.x + v.y * v.y + v.z * v.z + v.w * v.w;
    }
#pragma unroll
    for (int o = 16; o; o >>= 1) ss += __shfl_xor_sync(0xffffffffu, ss, o);

    __shared__ float red[8];
    __shared__ float s_inv;
    if ((threadIdx.x & 31) == 0) red[threadIdx.x >> 5] = ss;
    __syncthreads();
    if (threadIdx.x == 0) {
        float tot = 0.f;
        int nw = blockDim.x >> 5;
        for (int i = 0; i < nw; i++) tot += red[i];
        s_inv = rsqrtf(tot * (1.0f / C_DIM) + 1e-6f);
    }
    __syncthreads();
    float inv = s_inv;
    const float4* wr = reinterpret_cast<const float4*>(w);
    float4* outr = reinterpret_cast<float4*>(out + (size_t)row * C_DIM);
    for (int i = threadIdx.x; i < C_DIM / 4; i += blockDim.x) {
        float4 v = xr[i], ww = wr[i];
        v.x = to_tf32(v.x * inv * ww.x);
        v.y = to_tf32(v.y * inv * ww.y);
        v.z = to_tf32(v.z * inv * ww.z);
        v.w = to_tf32(v.w * inv * ww.w);
        outr[i] = v;
    }
}

// ---------------- RoPE + d-permutation + flash-operand rounding --------------
// Within each 8-group of headdim, permuted order (0,4,1,5,2,6,3,7): the tf32
// fragment pair (k=t, k=t+4) becomes adjacent -> float2 LDS in flash.
__global__ void rope_kernel(const float* __restrict__ q, const float* __restrict__ k,
                            float* __restrict__ v,
                            float* __restrict__ qp, float* __restrict__ kp)
{
    int idx = blockIdx.x * blockDim.x + threadIdx.x;
    if (idx >= T_SEQ * NHEADS * 32) return;
    int p = idx & 31;
    int h = (idx >> 5) & (NHEADS - 1);
    int t = idx >> 9;
    int j = p & 7;
    int i0 = (p & ~7) | ((j & 1) ? ((j >> 1) + 4) : (j >> 1));   // source index
    float freq = powf(10000.0f, -(float)(2 * i0) * (1.0f / 64.0f));
    float f = (float)t * freq;
    float s, c;
    sincosf(f, &s, &c);
    int base = t * C_DIM + h * HDIM;
    float q1 = q[base + i0], q2 = q[base + i0 + 32];
    qp[base + p]      = to_tf32((q1 * c - q2 * s) * 0.125f);
    qp[base + p + 32] = to_tf32((q2 * c + q1 * s) * 0.125f);
    float k1 = k[base + i0], k2 = k[base + i0 + 32];
    kp[base + p]      = to_tf32(k1 * c - k2 * s);
    kp[base + p + 32] = to_tf32(k2 * c + k1 * s);
    v[base + p]       = to_tf32(v[base + p]);
    v[base + p + 32]  = to_tf32(v[base + p + 32]);
}

// ---------------- Flash attention on tensor cores ----------------------------
// Br=Bc=64, 4 warps, 1-term tf32, occ=3.
// Per-plane strides chosen for conflict-free access patterns:
//   Q/K planes: stride 72 (== 8 mod 32) -> float2 fragment LDS conflict-free
//   P plane   : stride 68 (== 4 mod 32) -> scalar reads conflict-free
//   V plane   : stride 72               -> scalar reads (k-indexed) conflict-free
#define FQK_STR 72
#define FP_STR  68
#define FV_STR  72
#define F_SMEM_BYTES ((64 * (2 * FQK_STR + FP_STR + FV_STR)) * 4)   // 72704

__global__ __launch_bounds__(128, 3)
void flash_mma_kernel(const float* __restrict__ Qg, const float* __restrict__ Kg,
                      const float* __restrict__ Vg, float* __restrict__ Og)
{
    extern __shared__ float sm[];
    float* Qs = sm;                      // [64][FQK_STR]
    float* Kh = Qs + 64 * FQK_STR;       // [64][FQK_STR]
    float* Ps = Kh + 64 * FQK_STR;       // [64][FP_STR]
    float* Vs = Ps + 64 * FP_STR;        // [64][FV_STR]
    uint32_t kh_base = smem_u32(Kh);
    uint32_t vs_base = smem_u32(Vs);

    int qt = (gridDim.x - 1) - blockIdx.x;   // heavy tiles first
    int h  = blockIdx.y;
    int tid = threadIdx.x;
    int wid = tid >> 5;
    int lane = tid & 31;
    int gid = lane >> 2;
    int tig = lane & 3;
    int wr0 = wid * 16;

    // ---- load Q tile (pre-permuted/scaled/rounded) ----
#pragma unroll
    for (int v = 0; v < 8; v++) {
        int i = tid + v * 128;
        int row = i >> 4;
        int c4 = i & 15;
        *reinterpret_cast<float4*>(Qs + row * FQK_STR + c4 * 4) =
            *reinterpret_cast<const float4*>(
                Qg + (size_t)(qt * 64 + row) * C_DIM + h * HDIM + c4 * 4);
    }

    float oacc[8][4];
#pragma unroll
    for (int ni = 0; ni < 8; ni++)
#pragma unroll
        for (int e = 0; e < 4; e++) oacc[ni][e] = 0.f;
    float m0 = -INFINITY, m1 = -INFINITY;
    float l0 = 0.f, l1 = 0.f;

    for (int j = 0; j <= qt; j++) {
        __syncthreads();

        // ---- stage K and V tiles via cp.async (pre-rounded data) ----
#pragma unroll
        for (int t = 0; t < 8; t++) {
            int i = tid + t * 128;
            int row = i >> 4;
            int c4 = i & 15;
            const float* kg = Kg + (size_t)(j * 64 + row) * C_DIM + h * HDIM + c4 * 4;
            const float* vg = Vg + (size_t)(j * 64 + row) * C_DIM + h * HDIM + c4 * 4;
            cp_async16(kh_base + (uint32_t)(row * FQK_STR + c4 * 4) * 4u, kg);
            cp_async16(vs_base + (uint32_t)(row * FV_STR + c4 * 4) * 4u, vg);
        }
        cp_commit();
        cp_wait<0>();
        __syncthreads();

        // ---- S = Q K^T (conflict-free float2 fragment loads) ----
        float sacc[8][4];
#pragma unroll
        for (int ni = 0; ni < 8; ni++)
#pragma unroll
            for (int e = 0; e < 4; e++) sacc[ni][e] = 0.f;

#pragma unroll
        for (int kk = 0; kk < 8; kk++) {
            int kb = kk * 8;
            int abase = (wr0 + gid) * FQK_STR + kb + 2 * tig;
            float2 qA = *reinterpret_cast<const float2*>(Qs + abase);              // a0,a2
            float2 qB = *reinterpret_cast<const float2*>(Qs + abase + 8 * FQK_STR); // a1,a3
#pragma unroll
            for (int ni = 0; ni < 8; ni++) {
                float2 b = *reinterpret_cast<const float2*>(
                    Kh + (ni * 8 + gid) * FQK_STR + kb + 2 * tig);                  // b0,b1
                mma_tf32(sacc[ni], qA.x, qB.x, qA.y, qB.y, b.x, b.y);
            }
        }

        if (j == qt) {
#pragma unroll
            for (int ni = 0; ni < 8; ni++) {
                int c0 = ni * 8 + 2 * tig;
                int rA = wr0 + gid, rB = wr0 + gid + 8;
                if (c0 > rA)     sacc[ni][0] = -INFINITY;
                if (c0 + 1 > rA) sacc[ni][1] = -INFINITY;
                if (c0 > rB)     sacc[ni][2] = -INFINITY;
                if (c0 + 1 > rB) sacc[ni][3] = -INFINITY;
            }
        }

        float rm0 = -INFINITY, rm1 = -INFINITY;
#pragma unroll
        for (int ni = 0; ni < 8; ni++) {
            rm0 = fmaxf(rm0, fmaxf(sacc[ni][0], sacc[ni][1]));
            rm1 = fmaxf(rm1, fmaxf(sacc[ni][2], sacc[ni][3]));
        }
        rm0 = fmaxf(rm0, __shfl_xor_sync(0xffffffffu, rm0, 1));
        rm0 = fmaxf(rm0, __shfl_xor_sync(0xffffffffu, rm0, 2));
        rm1 = fmaxf(rm1, __shfl_xor_sync(0xffffffffu, rm1, 1));
        rm1 = fmaxf(rm1, __shfl_xor_sync(0xffffffffu, rm1, 2));

        float mn0 = fmaxf(m0, rm0);
        float mn1 = fmaxf(m1, rm1);
        float alpha0 = __expf(m0 - mn0);
        float alpha1 = __expf(m1 - mn1);
        m0 = mn0; m1 = mn1;

        float rs0 = 0.f, rs1 = 0.f;
#pragma unroll
        for (int ni = 0; ni < 8; ni++) {
            float p0 = __expf(sacc[ni][0] - mn0);
            float p1 = __expf(sacc[ni][1] - mn0);
            float p2 = __expf(sacc[ni][2] - mn1);
            float p3 = __expf(sacc[ni][3] - mn1);
            rs0 += p0 + p1;
            rs1 += p2 + p3;
            int c0 = ni * 8 + 2 * tig;
            *reinterpret_cast<float2*>(Ps + (wr0 + gid) * FP_STR + c0) =
                make_float2(to_tf32(p0), to_tf32(p1));
            *reinterpret_cast<float2*>(Ps + (wr0 + gid + 8) * FP_STR + c0) =
                make_float2(to_tf32(p2), to_tf32(p3));
        }
        rs0 += __shfl_xor_sync(0xffffffffu, rs0, 1);
        rs0 += __shfl_xor_sync(0xffffffffu, rs0, 2);
        rs1 += __shfl_xor_sync(0xffffffffu, rs1, 1);
        rs1 += __shfl_xor_sync(0xffffffffu, rs1, 2);
        l0 = l0 * alpha0 + rs0;
        l1 = l1 * alpha1 + rs1;

#pragma unroll
        for (int ni = 0; ni < 8; ni++) {
            oacc[ni][0] *= alpha0; oacc[ni][1] *= alpha0;
            oacc[ni][2] *= alpha1; oacc[ni][3] *= alpha1;
        }
        __syncwarp();

        // ---- O += P V (scalar paths, conflict-free strides) ----
#pragma unroll
        for (int kk = 0; kk < 8; kk++) {
            int kb = kk * 8;
            int abase = (wr0 + gid) * FP_STR + kb + tig;
            float a0 = Ps[abase];
            float a1 = Ps[abase + 8 * FP_STR];
            float a2 = Ps[abase + 4];
            float a3 = Ps[abase + 8 * FP_STR + 4];
#pragma unroll
            for (int ni = 0; ni < 8; ni++) {
                float b0 = Vs[(kb + tig) * FV_STR + ni * 8 + gid];
                float b1 = Vs[(kb + tig + 4) * FV_STR + ni * 8 + gid];
                mma_tf32(oacc[ni], a0, a1, a2, a3, b0, b1);
            }
        }
    }

    float invl0 = 1.f / l0;
    float invl1 = 1.f / l1;
    int row0 = qt * 64 + wr0 + gid;
    int row1 = row0 + 8;
#pragma unroll
    for (int ni = 0; ni < 8; ni++) {
        int col = h * HDIM + ni * 8 + 2 * tig;
        *reinterpret_cast<float2*>(Og + (size_t)row0 * C_DIM + col) =
            make_float2(to_tf32(oacc[ni][0] * invl0), to_tf32(oacc[ni][1] * invl0));
        *reinterpret_cast<float2*>(Og + (size_t)row1 * C_DIM + col) =
            make_float2(to_tf32(oacc[ni][2] * invl1), to_tf32(oacc[ni][3] * invl1));
    }
}

// ---------------- launch -----------------------------------------------------
extern "C" void kernel_launch(void* const* d_in, const int* in_sizes, int n_in,
                              void* d_out, int out_size)
{
    const float* x      = (const float*)d_in[0];
    const float* wq     = (const float*)d_in[1];
    const float* wk     = (const float*)d_in[2];
    const float* wv     = (const float*)d_in[3];
    const float* wo     = (const float*)d_in[4];
    const float* norm_w = (const float*)d_in[5];
    float* out = (float*)d_out;

    float *normed, *q, *k, *v, *qp, *kp, *att, *wr;
    cudaGetSymbolAddress((void**)&normed, g_normed);
    cudaGetSymbolAddress((void**)&q,      g_q);
    cudaGetSymbolAddress((void**)&k,      g_k);
    cudaGetSymbolAddress((void**)&v,      g_v);
    cudaGetSymbolAddress((void**)&qp,     g_qp);
    cudaGetSymbolAddress((void**)&kp,     g_kp);
    cudaGetSymbolAddress((void**)&att,    g_att);
    cudaGetSymbolAddress((void**)&wr,     g_wr);
    float* wqr = wr + 0 * C_DIM * C_DIM;
    float* wkr = wr + 1 * C_DIM * C_DIM;
    float* wvr = wr + 2 * C_DIM * C_DIM;
    float* wor = wr + 3 * C_DIM * C_DIM;

    // 0) round all 4 weight matrices to tf32 in one batched launch
    int n4 = C_DIM * C_DIM / 4;
    dim3 rg((n4 + 255) / 256, 4);
    round_weights_kernel<<<rg, 256>>>(wq, wk, wv, wo, wr, n4);

    // 1) RMSNorm (emits tf32-rounded A operand)
    rmsnorm_kernel<<<T_SEQ, 256>>>(x, norm_w, normed);

    // 2) Q/K/V projections: one batched launch
    cudaFuncSetAttribute(gemm_qkv_kernel, cudaFuncAttributeMaxDynamicSharedMemorySize,
                         G_SMEM_TOTAL);
    cudaFuncSetAttribute(gemm_mma_kernel, cudaFuncAttributeMaxDynamicSharedMemorySize,
                         G_SMEM_TOTAL);
    dim3 gqkv(C_DIM / G_BN, T_SEQ / G_BM, 3);
    gemm_qkv_kernel<<<gqkv, 256, G_SMEM_TOTAL>>>(normed, wqr, wkr, wvr, q, k, v);

    // 3) RoPE + d-permutation + rounding for flash
    int nrope = T_SEQ * NHEADS * 32;
    rope_kernel<<<(nrope + 255) / 256, 256>>>(q, k, v, qp, kp);

    // 4) causal flash attention (permuted Q/K, conflict-free float2 loads)
    cudaFuncSetAttribute(flash_mma_kernel, cudaFuncAttributeMaxDynamicSharedMemorySize,
                         F_SMEM_BYTES);
    dim3 fgrid(T_SEQ / 64, NHEADS);
    flash_mma_kernel<<<fgrid, 128, F_SMEM_BYTES>>>(qp, kp, v, att);

    // 5) output projection + residual
    dim3 gdim(C_DIM / G_BN, T_SEQ / G_BM);
    gemm_mma_kernel<<<gdim, 256, G_SMEM_TOTAL>>>(att, wor, x, out, T_SEQ, C_DIM, C_DIM);
}